// round 2
// baseline (speedup 1.0000x reference)
#include <cuda_runtime.h>
#include <cstdint>
#include <cstddef>

// Problem dims
#define BB   256      // batch
#define TT   512      // time
#define OBS  64
#define HH   256      // hidden
#define G3   768      // 3*H

typedef unsigned long long u64;

// ---------------- scratch (device globals: allocation-free) ----------------
__device__ float g_xg[(size_t)BB * TT * G3];   // 402 MB: gate pre-activations (reused for both layers)
__device__ float g_y0[(size_t)BB * TT * HH];   // 134 MB: layer-0 outputs

// ---------------- f32x2 packed-fp32 helpers (sm_100+) ----------------
__device__ __forceinline__ u64 dupf(float a) {
    u64 r; asm("mov.b64 %0, {%1,%1};" : "=l"(r) : "f"(a)); return r;
}
__device__ __forceinline__ u64 pk2(float lo, float hi) {
    u64 r; asm("mov.b64 %0, {%1,%2};" : "=l"(r) : "f"(lo), "f"(hi)); return r;
}
__device__ __forceinline__ float2 unpk(u64 v) {
    float2 f; asm("mov.b64 {%0,%1}, %2;" : "=f"(f.x), "=f"(f.y) : "l"(v)); return f;
}
__device__ __forceinline__ u64 f2fma(u64 a, u64 b, u64 c) {
    u64 d; asm("fma.rn.f32x2 %0, %1, %2, %3;" : "=l"(d) : "l"(a), "l"(b), "l"(c)); return d;
}
__device__ __forceinline__ float sigmf(float x) {
    return 1.0f / (1.0f + __expf(-x));
}

// =====================================================================
// Projection GEMM: C[M][768] = A[M][K] @ W[768][K]^T + bias[768]
// BM=128, BN=64, BK=16; 256 threads; per-thread 8 rows x 4 cols (2 f32x2 pairs)
// =====================================================================
#define PBM 128
#define PBN 64
#define PBK 16

__global__ void __launch_bounds__(256) proj_kernel(
    const float* __restrict__ A, const float* __restrict__ Wt,
    const float* __restrict__ bias, float* __restrict__ C, int K)
{
    __shared__ float As[2][PBK][PBM];   // transposed A tile: As[k][m]
    __shared__ float Wsf[2][PBK][PBN];  // W tile: Wsf[k][n]

    const int tid = threadIdx.x;
    const int tx = tid & 15;            // 0..15 -> cols 4*tx..4*tx+3
    const int ty = tid >> 4;            // 0..15 -> rows 8*ty..8*ty+7
    const int m0 = blockIdx.y * PBM;    // y = m-tile (x fastest = n-tile for A reuse in L2)
    const int n0 = blockIdx.x * PBN;

    // loader mapping: 64 rows x 4 k-chunks covered by 256 threads
    const int lrow = tid >> 2;          // 0..63
    const int lk4  = (tid & 3) << 2;    // 0,4,8,12
    const float* Ag0 = A  + (size_t)(m0 + lrow)      * K + lk4;
    const float* Ag1 = A  + (size_t)(m0 + lrow + 64) * K + lk4;
    const float* Wg  = Wt + (size_t)(n0 + lrow)      * K + lk4;

    u64 acc[8][2];
    #pragma unroll
    for (int i = 0; i < 8; ++i) { acc[i][0] = 0ULL; acc[i][1] = 0ULL; }

    const int panels = K >> 4;

    // prologue: panel 0 -> buf 0
    {
        float4 va0 = *(const float4*)(Ag0);
        float4 va1 = *(const float4*)(Ag1);
        float4 vw  = *(const float4*)(Wg);
        As[0][lk4+0][lrow] = va0.x; As[0][lk4+1][lrow] = va0.y;
        As[0][lk4+2][lrow] = va0.z; As[0][lk4+3][lrow] = va0.w;
        As[0][lk4+0][lrow+64] = va1.x; As[0][lk4+1][lrow+64] = va1.y;
        As[0][lk4+2][lrow+64] = va1.z; As[0][lk4+3][lrow+64] = va1.w;
        Wsf[0][lk4+0][lrow] = vw.x; Wsf[0][lk4+1][lrow] = vw.y;
        Wsf[0][lk4+2][lrow] = vw.z; Wsf[0][lk4+3][lrow] = vw.w;
    }
    __syncthreads();

    for (int p = 0; p < panels; ++p) {
        const int buf = p & 1;
        float4 na0, na1, nw;
        const bool more = (p + 1 < panels);
        if (more) {
            const int k0 = (p + 1) << 4;
            na0 = *(const float4*)(Ag0 + k0);
            na1 = *(const float4*)(Ag1 + k0);
            nw  = *(const float4*)(Wg  + k0);
        }
        #pragma unroll
        for (int k = 0; k < PBK; ++k) {
            float4 a0 = *(const float4*)&As[buf][k][ty * 8];
            float4 a1 = *(const float4*)&As[buf][k][ty * 8 + 4];
            ulonglong2 w = *(const ulonglong2*)&Wsf[buf][k][tx * 4];
            u64 d;
            d = dupf(a0.x); acc[0][0]=f2fma(d,w.x,acc[0][0]); acc[0][1]=f2fma(d,w.y,acc[0][1]);
            d = dupf(a0.y); acc[1][0]=f2fma(d,w.x,acc[1][0]); acc[1][1]=f2fma(d,w.y,acc[1][1]);
            d = dupf(a0.z); acc[2][0]=f2fma(d,w.x,acc[2][0]); acc[2][1]=f2fma(d,w.y,acc[2][1]);
            d = dupf(a0.w); acc[3][0]=f2fma(d,w.x,acc[3][0]); acc[3][1]=f2fma(d,w.y,acc[3][1]);
            d = dupf(a1.x); acc[4][0]=f2fma(d,w.x,acc[4][0]); acc[4][1]=f2fma(d,w.y,acc[4][1]);
            d = dupf(a1.y); acc[5][0]=f2fma(d,w.x,acc[5][0]); acc[5][1]=f2fma(d,w.y,acc[5][1]);
            d = dupf(a1.z); acc[6][0]=f2fma(d,w.x,acc[6][0]); acc[6][1]=f2fma(d,w.y,acc[6][1]);
            d = dupf(a1.w); acc[7][0]=f2fma(d,w.x,acc[7][0]); acc[7][1]=f2fma(d,w.y,acc[7][1]);
        }
        if (more) {
            const int nb = buf ^ 1;
            As[nb][lk4+0][lrow] = na0.x; As[nb][lk4+1][lrow] = na0.y;
            As[nb][lk4+2][lrow] = na0.z; As[nb][lk4+3][lrow] = na0.w;
            As[nb][lk4+0][lrow+64] = na1.x; As[nb][lk4+1][lrow+64] = na1.y;
            As[nb][lk4+2][lrow+64] = na1.z; As[nb][lk4+3][lrow+64] = na1.w;
            Wsf[nb][lk4+0][lrow] = nw.x; Wsf[nb][lk4+1][lrow] = nw.y;
            Wsf[nb][lk4+2][lrow] = nw.z; Wsf[nb][lk4+3][lrow] = nw.w;
        }
        __syncthreads();
    }

    // epilogue: add bias, write C
    const float4 bv = *(const float4*)&bias[n0 + tx * 4];
    #pragma unroll
    for (int i = 0; i < 8; ++i) {
        float2 v0 = unpk(acc[i][0]);
        float2 v1 = unpk(acc[i][1]);
        float4 o;
        o.x = v0.x + bv.x; o.y = v0.y + bv.y;
        o.z = v1.x + bv.z; o.w = v1.y + bv.w;
        const int m = m0 + ty * 8 + i;
        *(float4*)&C[(size_t)m * G3 + n0 + tx * 4] = o;
    }
}

// =====================================================================
// Recurrent scan: batch-partitioned (Bb=4 rows/block, 64 blocks, zero
// inter-block sync). Thread j owns hidden unit j for all 4 rows.
// h packed as f32x2 pairs (rows 0/1 and 2/3). W_hh k<KC cached in smem.
// =====================================================================
#define KC 64
#define WSTR 68                          // smem row stride (==4 mod 32 -> conflict-free LDS.128)
#define SCAN_DSMEM (G3 * WSTR * 4)       // 208896 B

struct Acc6 { u64 r0, r1, z0, z1, n0, n1; };

__device__ __forceinline__ void scan_chunk(
    const float4 wr, const float4 wz, const float4 wn,
    const u64* __restrict__ h0p, const u64* __restrict__ h1p, int k, Acc6& A)
{
    ulonglong2 ha = *(const ulonglong2*)(h0p + k);
    ulonglong2 hb = *(const ulonglong2*)(h0p + k + 2);
    ulonglong2 hc = *(const ulonglong2*)(h1p + k);
    ulonglong2 hd = *(const ulonglong2*)(h1p + k + 2);
    u64 d;
    d = dupf(wr.x); A.r0 = f2fma(d, ha.x, A.r0); A.r1 = f2fma(d, hc.x, A.r1);
    d = dupf(wr.y); A.r0 = f2fma(d, ha.y, A.r0); A.r1 = f2fma(d, hc.y, A.r1);
    d = dupf(wr.z); A.r0 = f2fma(d, hb.x, A.r0); A.r1 = f2fma(d, hd.x, A.r1);
    d = dupf(wr.w); A.r0 = f2fma(d, hb.y, A.r0); A.r1 = f2fma(d, hd.y, A.r1);
    d = dupf(wz.x); A.z0 = f2fma(d, ha.x, A.z0); A.z1 = f2fma(d, hc.x, A.z1);
    d = dupf(wz.y); A.z0 = f2fma(d, ha.y, A.z0); A.z1 = f2fma(d, hc.y, A.z1);
    d = dupf(wz.z); A.z0 = f2fma(d, hb.x, A.z0); A.z1 = f2fma(d, hd.x, A.z1);
    d = dupf(wz.w); A.z0 = f2fma(d, hb.y, A.z0); A.z1 = f2fma(d, hd.y, A.z1);
    d = dupf(wn.x); A.n0 = f2fma(d, ha.x, A.n0); A.n1 = f2fma(d, hc.x, A.n1);
    d = dupf(wn.y); A.n0 = f2fma(d, ha.y, A.n0); A.n1 = f2fma(d, hc.y, A.n1);
    d = dupf(wn.z); A.n0 = f2fma(d, hb.x, A.n0); A.n1 = f2fma(d, hd.x, A.n1);
    d = dupf(wn.w); A.n0 = f2fma(d, hb.y, A.n0); A.n1 = f2fma(d, hd.y, A.n1);
}

template<bool WRITE_Y>
__global__ void __launch_bounds__(256, 1) scan_kernel(
    const float* __restrict__ xg, const float* __restrict__ Whh,
    const float* __restrict__ bhh, float* __restrict__ y, float* __restrict__ hout)
{
    extern __shared__ float Ws[];                 // [G3][WSTR] cached W_hh columns k<KC
    __shared__ u64 h2[2][2][HH];                  // [buf][pair][k] : (h[2p],h[2p+1]) packed

    const int j = threadIdx.x;                    // hidden unit
    const int bb0 = blockIdx.x * 4;               // batch base

    // cache W_hh[:, 0:KC) into smem
    for (int idx = j; idx < G3 * (KC / 4); idx += 256) {
        const int g  = idx >> 4;                  // row
        const int kc = (idx & 15) << 2;           // k chunk
        *(float4*)&Ws[g * WSTR + kc] = *(const float4*)&Whh[(size_t)g * HH + kc];
    }
    h2[0][0][j] = 0ULL;
    h2[0][1][j] = 0ULL;

    const float br = bhh[j], bz = bhh[j + HH], bn = bhh[j + 2 * HH];
    const float* __restrict__ WgR = Whh + (size_t)j * HH;
    const float* __restrict__ WgZ = Whh + (size_t)(j + HH) * HH;
    const float* __restrict__ WgN = Whh + (size_t)(j + 2 * HH) * HH;
    const float* WsR = Ws + j * WSTR;
    const float* WsZ = Ws + (j + HH) * WSTR;
    const float* WsN = Ws + (j + 2 * HH) * WSTR;

    __syncthreads();
    int buf = 0;

    for (int t = 0; t < TT; ++t) {
        // prefetch this step's gate pre-activations (independent of k-loop)
        float xr[4], xz[4], xn[4];
        #pragma unroll
        for (int b = 0; b < 4; ++b) {
            const float* p = xg + ((size_t)(bb0 + b) * TT + t) * G3;
            xr[b] = p[j]; xz[b] = p[j + HH]; xn[b] = p[j + 2 * HH];
        }

        Acc6 A; A.r0 = A.r1 = A.z0 = A.z1 = A.n0 = A.n1 = 0ULL;
        const u64* h0p = h2[buf][0];
        const u64* h1p = h2[buf][1];

        // k < KC : W from smem
        #pragma unroll 4
        for (int k = 0; k < KC; k += 4) {
            float4 wr = *(const float4*)(WsR + k);
            float4 wz = *(const float4*)(WsZ + k);
            float4 wn = *(const float4*)(WsN + k);
            scan_chunk(wr, wz, wn, h0p, h1p, k, A);
        }
        // k >= KC : W streamed from L2 (L1-friendly: each 128B line feeds 8 chunks of same thread)
        #pragma unroll 4
        for (int k = KC; k < HH; k += 4) {
            float4 wr = *(const float4*)(WgR + k);
            float4 wz = *(const float4*)(WgZ + k);
            float4 wn = *(const float4*)(WgN + k);
            scan_chunk(wr, wz, wn, h0p, h1p, k, A);
        }

        // gates + state update
        float hr[4], hz[4], hn_[4];
        { float2 v = unpk(A.r0); hr[0]=v.x; hr[1]=v.y; v = unpk(A.r1); hr[2]=v.x; hr[3]=v.y; }
        { float2 v = unpk(A.z0); hz[0]=v.x; hz[1]=v.y; v = unpk(A.z1); hz[2]=v.x; hz[3]=v.y; }
        { float2 v = unpk(A.n0); hn_[0]=v.x; hn_[1]=v.y; v = unpk(A.n1); hn_[2]=v.x; hn_[3]=v.y; }
        float2 hp01 = unpk(h0p[j]);
        float2 hp23 = unpk(h1p[j]);
        float hprev[4] = { hp01.x, hp01.y, hp23.x, hp23.y };

        float hnew[4];
        #pragma unroll
        for (int b = 0; b < 4; ++b) {
            const float r = sigmf(xr[b] + hr[b] + br);
            const float z = sigmf(xz[b] + hz[b] + bz);
            const float n = tanhf(xn[b] + r * (hn_[b] + bn));
            hnew[b] = (1.0f - z) * n + z * hprev[b];
            if (WRITE_Y)
                y[((size_t)(bb0 + b) * TT + t) * HH + j] = hnew[b];
        }

        h2[buf ^ 1][0][j] = pk2(hnew[0], hnew[1]);
        h2[buf ^ 1][1][j] = pk2(hnew[2], hnew[3]);
        __syncthreads();
        buf ^= 1;
    }

    if (!WRITE_Y) {
        float2 a = unpk(h2[buf][0][j]);
        float2 b2 = unpk(h2[buf][1][j]);
        hout[(size_t)(bb0 + 0) * HH + j] = a.x;
        hout[(size_t)(bb0 + 1) * HH + j] = a.y;
        hout[(size_t)(bb0 + 2) * HH + j] = b2.x;
        hout[(size_t)(bb0 + 3) * HH + j] = b2.y;
    }
}

// =====================================================================
// launch
// =====================================================================
extern "C" void kernel_launch(void* const* d_in, const int* in_sizes, int n_in,
                              void* d_out, int out_size)
{
    const float* obs   = (const float*)d_in[0];
    const float* w_ih0 = (const float*)d_in[1];
    const float* w_hh0 = (const float*)d_in[2];
    const float* b_ih0 = (const float*)d_in[3];
    const float* b_hh0 = (const float*)d_in[4];
    const float* w_ih1 = (const float*)d_in[5];
    const float* w_hh1 = (const float*)d_in[6];
    const float* b_ih1 = (const float*)d_in[7];
    const float* b_hh1 = (const float*)d_in[8];
    float* out = (float*)d_out;

    void* xg_p = nullptr; cudaGetSymbolAddress(&xg_p, g_xg);
    void* y0_p = nullptr; cudaGetSymbolAddress(&y0_p, g_y0);
    float* xg = (float*)xg_p;
    float* y0 = (float*)y0_p;

    cudaFuncSetAttribute(scan_kernel<true>,  cudaFuncAttributeMaxDynamicSharedMemorySize, SCAN_DSMEM);
    cudaFuncSetAttribute(scan_kernel<false>, cudaFuncAttributeMaxDynamicSharedMemorySize, SCAN_DSMEM);

    const int M = BB * TT;                 // 131072
    dim3 pgrid(G3 / PBN, M / PBM);         // (12, 1024): n-tiles fastest -> A tile L2 reuse

    // layer 0: xg0 = obs @ W_ih0^T + b_ih0
    proj_kernel<<<pgrid, 256>>>(obs, w_ih0, b_ih0, xg, OBS);
    // layer 0 scan -> y0
    scan_kernel<true><<<BB / 4, 256, SCAN_DSMEM>>>(xg, w_hh0, b_hh0, y0, nullptr);
    // layer 1: xg1 = y0 @ W_ih1^T + b_ih1  (reuses g_xg)
    proj_kernel<<<pgrid, 256>>>(y0, w_ih1, b_ih1, xg, HH);
    // layer 1 scan -> final hidden
    scan_kernel<false><<<BB / 4, 256, SCAN_DSMEM>>>(xg, w_hh1, b_hh1, nullptr, out);
}

// round 3
// speedup vs baseline: 2.5664x; 2.5664x over previous
#include <cuda_runtime.h>
#include <cstdint>
#include <cstddef>

// Problem dims
#define BB   256      // batch
#define TT   512      // time
#define OBS  64
#define HH   256      // hidden
#define G3   768      // 3*H
#define HHQ  64       // HH/4 (k-quads)

typedef unsigned long long u64;

// ---------------- scratch (device globals: allocation-free) ----------------
__device__ float g_xg[(size_t)BB * TT * G3];   // 402 MB: gate pre-activations
__device__ float g_y0[(size_t)BB * TT * HH];   // 134 MB: layer-0 outputs
__device__ float g_wt[(size_t)HH * G3];        // 786 KB: transposed W_hh (k-major, quad-interleaved)

// ---------------- f32x2 packed-fp32 helpers (sm_100+) ----------------
__device__ __forceinline__ u64 dupf(float a) {
    u64 r; asm("mov.b64 %0, {%1,%1};" : "=l"(r) : "f"(a)); return r;
}
__device__ __forceinline__ u64 pk2(float lo, float hi) {
    u64 r; asm("mov.b64 %0, {%1,%2};" : "=l"(r) : "f"(lo), "f"(hi)); return r;
}
__device__ __forceinline__ float2 unpk(u64 v) {
    float2 f; asm("mov.b64 {%0,%1}, %2;" : "=f"(f.x), "=f"(f.y) : "l"(v)); return f;
}
__device__ __forceinline__ u64 f2fma(u64 a, u64 b, u64 c) {
    u64 d; asm("fma.rn.f32x2 %0, %1, %2, %3;" : "=l"(d) : "l"(a), "l"(b), "l"(c)); return d;
}
__device__ __forceinline__ u64 add2(u64 a, u64 b) {
    u64 d; asm("add.rn.f32x2 %0, %1, %2;" : "=l"(d) : "l"(a), "l"(b)); return d;
}
__device__ __forceinline__ float sigmf(float x) {
    return 1.0f / (1.0f + __expf(-x));
}

// =====================================================================
// W_hh transpose: Whh[g][k] (g-major) -> Wt4 quad-interleaved:
//   Wt4[(k>>2)*G3*4 + g*4 + (k&3)]  == float4 view: wt4v[k/4][g]
// =====================================================================
__global__ void transpose_whh(const float* __restrict__ W, float* __restrict__ Wt4)
{
    const int g = blockIdx.x;        // 0..767
    const int k = threadIdx.x;       // 0..255
    const float v = W[(size_t)g * HH + k];   // coalesced read
    Wt4[(size_t)(k >> 2) * (G3 * 4) + g * 4 + (k & 3)] = v;
}

// =====================================================================
// Projection GEMM: C[M][768] = A[M][K] @ W[768][K]^T + bias[768]
// =====================================================================
#define PBM 128
#define PBN 64
#define PBK 16

__global__ void __launch_bounds__(256) proj_kernel(
    const float* __restrict__ A, const float* __restrict__ Wt,
    const float* __restrict__ bias, float* __restrict__ C, int K)
{
    __shared__ float As[2][PBK][PBM];
    __shared__ float Wsf[2][PBK][PBN];

    const int tid = threadIdx.x;
    const int tx = tid & 15;
    const int ty = tid >> 4;
    const int m0 = blockIdx.y * PBM;
    const int n0 = blockIdx.x * PBN;

    const int lrow = tid >> 2;
    const int lk4  = (tid & 3) << 2;
    const float* Ag0 = A  + (size_t)(m0 + lrow)      * K + lk4;
    const float* Ag1 = A  + (size_t)(m0 + lrow + 64) * K + lk4;
    const float* Wg  = Wt + (size_t)(n0 + lrow)      * K + lk4;

    u64 acc[8][2];
    #pragma unroll
    for (int i = 0; i < 8; ++i) { acc[i][0] = 0ULL; acc[i][1] = 0ULL; }

    const int panels = K >> 4;
    {
        float4 va0 = *(const float4*)(Ag0);
        float4 va1 = *(const float4*)(Ag1);
        float4 vw  = *(const float4*)(Wg);
        As[0][lk4+0][lrow] = va0.x; As[0][lk4+1][lrow] = va0.y;
        As[0][lk4+2][lrow] = va0.z; As[0][lk4+3][lrow] = va0.w;
        As[0][lk4+0][lrow+64] = va1.x; As[0][lk4+1][lrow+64] = va1.y;
        As[0][lk4+2][lrow+64] = va1.z; As[0][lk4+3][lrow+64] = va1.w;
        Wsf[0][lk4+0][lrow] = vw.x; Wsf[0][lk4+1][lrow] = vw.y;
        Wsf[0][lk4+2][lrow] = vw.z; Wsf[0][lk4+3][lrow] = vw.w;
    }
    __syncthreads();

    for (int p = 0; p < panels; ++p) {
        const int buf = p & 1;
        float4 na0, na1, nw;
        const bool more = (p + 1 < panels);
        if (more) {
            const int k0 = (p + 1) << 4;
            na0 = *(const float4*)(Ag0 + k0);
            na1 = *(const float4*)(Ag1 + k0);
            nw  = *(const float4*)(Wg  + k0);
        }
        #pragma unroll
        for (int k = 0; k < PBK; ++k) {
            float4 a0 = *(const float4*)&As[buf][k][ty * 8];
            float4 a1 = *(const float4*)&As[buf][k][ty * 8 + 4];
            ulonglong2 w = *(const ulonglong2*)&Wsf[buf][k][tx * 4];
            u64 d;
            d = dupf(a0.x); acc[0][0]=f2fma(d,w.x,acc[0][0]); acc[0][1]=f2fma(d,w.y,acc[0][1]);
            d = dupf(a0.y); acc[1][0]=f2fma(d,w.x,acc[1][0]); acc[1][1]=f2fma(d,w.y,acc[1][1]);
            d = dupf(a0.z); acc[2][0]=f2fma(d,w.x,acc[2][0]); acc[2][1]=f2fma(d,w.y,acc[2][1]);
            d = dupf(a0.w); acc[3][0]=f2fma(d,w.x,acc[3][0]); acc[3][1]=f2fma(d,w.y,acc[3][1]);
            d = dupf(a1.x); acc[4][0]=f2fma(d,w.x,acc[4][0]); acc[4][1]=f2fma(d,w.y,acc[4][1]);
            d = dupf(a1.y); acc[5][0]=f2fma(d,w.x,acc[5][0]); acc[5][1]=f2fma(d,w.y,acc[5][1]);
            d = dupf(a1.z); acc[6][0]=f2fma(d,w.x,acc[6][0]); acc[6][1]=f2fma(d,w.y,acc[6][1]);
            d = dupf(a1.w); acc[7][0]=f2fma(d,w.x,acc[7][0]); acc[7][1]=f2fma(d,w.y,acc[7][1]);
        }
        if (more) {
            const int nb = buf ^ 1;
            As[nb][lk4+0][lrow] = na0.x; As[nb][lk4+1][lrow] = na0.y;
            As[nb][lk4+2][lrow] = na0.z; As[nb][lk4+3][lrow] = na0.w;
            As[nb][lk4+0][lrow+64] = na1.x; As[nb][lk4+1][lrow+64] = na1.y;
            As[nb][lk4+2][lrow+64] = na1.z; As[nb][lk4+3][lrow+64] = na1.w;
            Wsf[nb][lk4+0][lrow] = nw.x; Wsf[nb][lk4+1][lrow] = nw.y;
            Wsf[nb][lk4+2][lrow] = nw.z; Wsf[nb][lk4+3][lrow] = nw.w;
        }
        __syncthreads();
    }

    const float4 bv = *(const float4*)&bias[n0 + tx * 4];
    #pragma unroll
    for (int i = 0; i < 8; ++i) {
        float2 v0 = unpk(acc[i][0]);
        float2 v1 = unpk(acc[i][1]);
        float4 o;
        o.x = v0.x + bv.x; o.y = v0.y + bv.y;
        o.z = v1.x + bv.z; o.w = v1.y + bv.w;
        const int m = m0 + ty * 8 + i;
        *(float4*)&C[(size_t)m * G3 + n0 + tx * 4] = o;
    }
}

// =====================================================================
// Recurrent scan, coalesced k-major weights.
// 64 blocks x 768 threads. Thread tid = (gate, j): gate = tid>>8, j = tid&255.
// Each block owns 4 batch rows (packed as two f32x2 pairs).
// W residency: k-quads [0,17) smem, [17,21) registers, [21,64) streamed L2.
// =====================================================================
#define KCQ 17                           // quads cached in smem (k < 68)
#define KRQ 4                            // quads cached in regs  (k 68..83)
#define KSQ0 (KCQ + KRQ)                 // first streamed quad (21)
#define SCAN_DSMEM (KCQ * G3 * 16)       // 208896 B

template<bool WRITE_Y>
__global__ void __launch_bounds__(768, 1) scan_kernel(
    const float* __restrict__ xg, const float* __restrict__ wt4,
    const float* __restrict__ bhh, float* __restrict__ y, float* __restrict__ hout)
{
    extern __shared__ float4 Wsc[];        // [KCQ][G3] float4 (same layout as wt4)
    __shared__ ulonglong2 hsm[HH];         // per k: (pk2(h0,h1), pk2(h2,h3))
    __shared__ ulonglong2 gsum[G3];        // per (gate,j): packed gate dots

    const int tid  = threadIdx.x;
    const int gate = tid >> 8;
    const int bb0  = blockIdx.x * 4;

    const float4* __restrict__ wt4v = (const float4*)wt4;   // [HHQ][G3]

    // fill smem W cache (coalesced float4 copy)
    for (int i = tid; i < KCQ * G3; i += 768)
        Wsc[i] = wt4v[i];

    // register W cache for this thread's column g = tid
    float4 wreg[KRQ];
    #pragma unroll
    for (int q = 0; q < KRQ; ++q)
        wreg[q] = wt4v[(size_t)(KCQ + q) * G3 + tid];

    const float bias = bhh[tid];
    if (tid < HH) hsm[tid] = make_ulonglong2(0ULL, 0ULL);
    __syncthreads();

    const size_t STRB  = (size_t)TT * G3;   // xg batch stride
    const size_t STRBY = (size_t)TT * HH;   // y batch stride
    const float* xbase = xg + (size_t)bb0 * STRB;

    for (int t = 0; t < TT; ++t) {
        // --- prefetch this step's x terms (consumed at the end of the step) ---
        float x0=0.f, x1=0.f, x2=0.f, x3=0.f;
        float xn0=0.f, xn1=0.f, xn2=0.f, xn3=0.f;
        const size_t tofs = (size_t)t * G3;
        if (gate < 2) {                      // r/z gates: col == tid
            const float* p = xbase + tofs + tid;
            x0 = p[0]; x1 = p[STRB]; x2 = p[2*STRB]; x3 = p[3*STRB];
        }
        if (tid < HH) {                      // combine threads fetch xn
            const float* p = xbase + tofs + 2*HH + tid;
            xn0 = p[0]; xn1 = p[STRB]; xn2 = p[2*STRB]; xn3 = p[3*STRB];
        }

        // --- dot: acc[pair] over k, 2 interleaved chains per pair ---
        u64 aA0 = 0ULL, aA1 = 0ULL, aB0 = 0ULL, aB1 = 0ULL;

        #pragma unroll
        for (int q = 0; q < KCQ; ++q) {      // smem segment
            float4 w = Wsc[q * G3 + tid];
            ulonglong2 h0 = hsm[4*q+0], h1 = hsm[4*q+1];
            ulonglong2 h2 = hsm[4*q+2], h3 = hsm[4*q+3];
            u64 d;
            d = dupf(w.x); aA0 = f2fma(d, h0.x, aA0); aA1 = f2fma(d, h0.y, aA1);
            d = dupf(w.y); aB0 = f2fma(d, h1.x, aB0); aB1 = f2fma(d, h1.y, aB1);
            d = dupf(w.z); aA0 = f2fma(d, h2.x, aA0); aA1 = f2fma(d, h2.y, aA1);
            d = dupf(w.w); aB0 = f2fma(d, h3.x, aB0); aB1 = f2fma(d, h3.y, aB1);
        }
        #pragma unroll
        for (int q = 0; q < KRQ; ++q) {      // register segment
            float4 w = wreg[q];
            const int kb = 4 * (KCQ + q);
            ulonglong2 h0 = hsm[kb+0], h1 = hsm[kb+1];
            ulonglong2 h2 = hsm[kb+2], h3 = hsm[kb+3];
            u64 d;
            d = dupf(w.x); aA0 = f2fma(d, h0.x, aA0); aA1 = f2fma(d, h0.y, aA1);
            d = dupf(w.y); aB0 = f2fma(d, h1.x, aB0); aB1 = f2fma(d, h1.y, aB1);
            d = dupf(w.z); aA0 = f2fma(d, h2.x, aA0); aA1 = f2fma(d, h2.y, aA1);
            d = dupf(w.w); aB0 = f2fma(d, h3.x, aB0); aB1 = f2fma(d, h3.y, aB1);
        }
        #pragma unroll
        for (int q = KSQ0; q < HHQ; ++q) {   // streamed segment (L2-resident, coalesced)
            float4 w = wt4v[(size_t)q * G3 + tid];
            ulonglong2 h0 = hsm[4*q+0], h1 = hsm[4*q+1];
            ulonglong2 h2 = hsm[4*q+2], h3 = hsm[4*q+3];
            u64 d;
            d = dupf(w.x); aA0 = f2fma(d, h0.x, aA0); aA1 = f2fma(d, h0.y, aA1);
            d = dupf(w.y); aB0 = f2fma(d, h1.x, aB0); aB1 = f2fma(d, h1.y, aB1);
            d = dupf(w.z); aA0 = f2fma(d, h2.x, aA0); aA1 = f2fma(d, h2.y, aA1);
            d = dupf(w.w); aB0 = f2fma(d, h3.x, aB0); aB1 = f2fma(d, h3.y, aB1);
        }

        // fold bias (+x for r/z) and publish
        u64 s0 = add2(aA0, aB0);
        u64 s1 = add2(aA1, aB1);
        if (gate == 2) {
            u64 bb = dupf(bias);
            s0 = add2(s0, bb); s1 = add2(s1, bb);
        } else {
            s0 = add2(s0, pk2(x0 + bias, x1 + bias));
            s1 = add2(s1, pk2(x2 + bias, x3 + bias));
        }
        gsum[tid] = make_ulonglong2(s0, s1);
        __syncthreads();

        // --- combine (first 256 threads) ---
        if (tid < HH) {
            ulonglong2 Rv = gsum[tid];
            ulonglong2 Zv = gsum[HH + tid];
            ulonglong2 Nv = gsum[2*HH + tid];
            ulonglong2 hp = hsm[tid];
            float2 ra = unpk(Rv.x), rb = unpk(Rv.y);
            float2 za = unpk(Zv.x), zb = unpk(Zv.y);
            float2 na = unpk(Nv.x), nb = unpk(Nv.y);
            float2 ha = unpk(hp.x), hb = unpk(hp.y);
            float hr[4]  = {ra.x, ra.y, rb.x, rb.y};
            float hz[4]  = {za.x, za.y, zb.x, zb.y};
            float hn[4]  = {na.x, na.y, nb.x, nb.y};
            float hpv[4] = {ha.x, ha.y, hb.x, hb.y};
            float xn[4]  = {xn0, xn1, xn2, xn3};
            float hnew[4];
            #pragma unroll
            for (int b = 0; b < 4; ++b) {
                const float r = sigmf(hr[b]);
                const float z = sigmf(hz[b]);
                const float n = tanhf(xn[b] + r * hn[b]);
                hnew[b] = (1.0f - z) * n + z * hpv[b];
            }
            hsm[tid] = make_ulonglong2(pk2(hnew[0], hnew[1]), pk2(hnew[2], hnew[3]));
            if (WRITE_Y) {
                float* yp = y + (size_t)bb0 * STRBY + (size_t)t * HH + tid;
                yp[0] = hnew[0]; yp[STRBY] = hnew[1];
                yp[2*STRBY] = hnew[2]; yp[3*STRBY] = hnew[3];
            }
        }
        __syncthreads();
    }

    if (!WRITE_Y && tid < HH) {
        ulonglong2 hp = hsm[tid];
        float2 a = unpk(hp.x), b = unpk(hp.y);
        hout[(size_t)(bb0 + 0) * HH + tid] = a.x;
        hout[(size_t)(bb0 + 1) * HH + tid] = a.y;
        hout[(size_t)(bb0 + 2) * HH + tid] = b.x;
        hout[(size_t)(bb0 + 3) * HH + tid] = b.y;
    }
}

// =====================================================================
// launch
// =====================================================================
extern "C" void kernel_launch(void* const* d_in, const int* in_sizes, int n_in,
                              void* d_out, int out_size)
{
    const float* obs   = (const float*)d_in[0];
    const float* w_ih0 = (const float*)d_in[1];
    const float* w_hh0 = (const float*)d_in[2];
    const float* b_ih0 = (const float*)d_in[3];
    const float* b_hh0 = (const float*)d_in[4];
    const float* w_ih1 = (const float*)d_in[5];
    const float* w_hh1 = (const float*)d_in[6];
    const float* b_ih1 = (const float*)d_in[7];
    const float* b_hh1 = (const float*)d_in[8];
    float* out = (float*)d_out;

    void* xg_p = nullptr; cudaGetSymbolAddress(&xg_p, g_xg);
    void* y0_p = nullptr; cudaGetSymbolAddress(&y0_p, g_y0);
    void* wt_p = nullptr; cudaGetSymbolAddress(&wt_p, g_wt);
    float* xg = (float*)xg_p;
    float* y0 = (float*)y0_p;
    float* wt = (float*)wt_p;

    cudaFuncSetAttribute(scan_kernel<true>,  cudaFuncAttributeMaxDynamicSharedMemorySize, SCAN_DSMEM);
    cudaFuncSetAttribute(scan_kernel<false>, cudaFuncAttributeMaxDynamicSharedMemorySize, SCAN_DSMEM);

    const int M = BB * TT;                 // 131072
    dim3 pgrid(G3 / PBN, M / PBM);         // (12, 1024)

    // layer 0
    transpose_whh<<<G3, HH>>>(w_hh0, wt);
    proj_kernel<<<pgrid, 256>>>(obs, w_ih0, b_ih0, xg, OBS);
    scan_kernel<true><<<BB / 4, 768, SCAN_DSMEM>>>(xg, wt, b_hh0, y0, nullptr);
    // layer 1
    transpose_whh<<<G3, HH>>>(w_hh1, wt);
    proj_kernel<<<pgrid, 256>>>(y0, w_ih1, b_ih1, xg, HH);
    scan_kernel<false><<<BB / 4, 768, SCAN_DSMEM>>>(xg, wt, b_hh1, nullptr, out);
}